// round 14
// baseline (speedup 1.0000x reference)
#include <cuda_runtime.h>
#include <math.h>

#define N_NODES   100000
#define N_EDGES   1600000
#define F_DIM     64
#define C_CLS     10
#define G_GRAPHS  512
#define CAP       64        // max in-degree (Poisson mean 16; P(>64) ~ 1e-20)
#define NBLK      592       // 148 SMs x 4 co-resident blocks (launch_bounds)
#define TPB       256
#define NWARPS    (NBLK * TPB / 32)
#define LEAVES    37        // tree barrier: 592 = 37 leaves x 16 blocks
#define LEAF_SZ   16

// Scratch (device globals: zero-initialized at module load; no runtime alloc)
__device__ float    g_h0[N_NODES * F_DIM];
__device__ float    g_h1[N_NODES * F_DIM];
__device__ float    g_dinv[N_NODES];
__device__ int      g_cnt_in[N_NODES];     // invariant: zero at kernel entry
__device__ int2     g_adj[(size_t)N_NODES * CAP];   // {src, raw weight bits}
__device__ float    g_s[G_GRAPHS * F_DIM]; // invariant: zero at kernel entry
__device__ unsigned g_leaf[LEAVES];        // monotonic; never reset
__device__ unsigned g_root;                // monotonic; never reset

static __device__ __forceinline__ void red_add_v4(float* dst, float4 v) {
    asm volatile("red.global.add.v4.f32 [%0], {%1, %2, %3, %4};"
                 :: "l"(dst), "f"(v.x), "f"(v.y), "f"(v.z), "f"(v.w)
                 : "memory");
}

// Two-level grid barrier, monotonic counters (no reset across graph replays).
// Arrivals: 16 serialized atomics per leaf (37 leaves in parallel) + 37 on
// the root, vs 592 serialized on one address for a flat barrier. The wait
// polls the root with a volatile LOAD (reads don't serialize at the LTS).
static __device__ __forceinline__ void grid_barrier() {
    __threadfence();                 // release (all threads)
    __syncthreads();
    if (threadIdx.x == 0) {
        int leaf = blockIdx.x >> 4;                       // 16 blocks / leaf
        unsigned t = atomicAdd(&g_leaf[leaf], 1u);
        unsigned round = t >> 4;
        if ((t & (LEAF_SZ - 1u)) == LEAF_SZ - 1u)         // last in leaf
            atomicAdd(&g_root, 1u);
        unsigned target = (round + 1u) * LEAVES;
        volatile unsigned* r = &g_root;
        while (*r < target) __nanosleep(32);
    }
    __syncthreads();
    __threadfence();                 // acquire (all threads)
}

// ---------------------------------------------------------------------------
// Hop in SCALED representation: input is h_hat = dinv .* h.
//   acc    = h_hat[c] + sum_e ew * h_hat[src]
//   !POOL: h_hat_out[c] = dinv[c]^2 * acc
//   POOL:  h_final[c]   = dinv[c]   * acc  -> red-add into g_s[batch[c]]
template <bool POOL>
static __device__ void hop_phase(const float* __restrict__ hin,
                                 float* __restrict__ hout,
                                 const int* __restrict__ batch) {
    int gwarp = (blockIdx.x * TPB + threadIdx.x) >> 5;
    int lane = threadIdx.x & 31;
    int half = lane >> 4;
    int sub = lane & 15;
    const float4* __restrict__ hin4 = reinterpret_cast<const float4*>(hin);
    float4* __restrict__ hout4 = reinterpret_cast<float4*>(hout);

    for (int base = gwarp * 2; base < N_NODES; base += NWARPS * 2) {
        int n = base + half;   // N_NODES even -> both halves always valid

        float dv = g_dinv[n];
        float4 acc = hin4[(size_t)n * 16 + sub];   // self contribution

        int cnt = min(g_cnt_in[n], CAP);
        const int2* adj = g_adj + (size_t)n * CAP;

        for (int k = 0; k < cnt; k += 4) {
            int4 p0 = *reinterpret_cast<const int4*>(adj + k);
            int4 p1 = *reinterpret_cast<const int4*>(adj + k + 2);
            int   s[4] = { p0.x, p0.z, p1.x, p1.z };
            float w[4] = { __int_as_float(p0.y), __int_as_float(p0.w),
                           __int_as_float(p1.y), __int_as_float(p1.w) };

            float4 u[4];
#pragma unroll
            for (int i = 0; i < 4; i++) {
                if (k + i >= cnt) w[i] = 0.0f;          // neutralize overshoot
                unsigned su = (unsigned)s[i];
                int src = (su < (unsigned)N_NODES) ? (int)su : 0;
                u[i] = hin4[(size_t)src * 16 + sub];    // 4 gathers in flight
            }
#pragma unroll
            for (int i = 0; i < 4; i++) {
                acc.x = fmaf(w[i], u[i].x, acc.x);
                acc.y = fmaf(w[i], u[i].y, acc.y);
                acc.z = fmaf(w[i], u[i].z, acc.z);
                acc.w = fmaf(w[i], u[i].w, acc.w);
            }
        }

        float sc = POOL ? dv : (dv * dv);
        acc.x *= sc; acc.y *= sc; acc.z *= sc; acc.w *= sc;

        if (POOL) {
            int b = batch[n];
            red_add_v4(&g_s[b * F_DIM + sub * 4], acc);
        } else {
            hout4[(size_t)n * 16 + sub] = acc;
        }
    }
}

// ---------------------------------------------------------------------------
// ONE persistent kernel. Entry invariant: g_cnt_in and g_s are all zero
// (zero-init at load; re-established at the tail of every call).
__global__ void __launch_bounds__(TPB, 4)
sgc_persistent_kernel(const float* __restrict__ x,
                      const int* __restrict__ eidx,
                      const float* __restrict__ ew,
                      const int* __restrict__ batch,
                      const float* __restrict__ conv_w,
                      const float* __restrict__ conv_b,
                      const float* __restrict__ lin1_w,
                      const float* __restrict__ lin1_b,
                      const float* __restrict__ lin2_w,
                      const float* __restrict__ lin2_b,
                      float* __restrict__ out) {
    const int tid = blockIdx.x * TPB + threadIdx.x;
    const int stride = NBLK * TPB;
    const int* row = eidx;             // edge_index[0]
    const int* col = eidx + N_EDGES;   // edge_index[1]

    // ---- phase 1: build in-adjacency buckets (counters pre-zeroed) ----
    for (int e = tid; e < N_EDGES; e += stride) {
        int c = col[e];
        int i = atomicAdd(&g_cnt_in[c], 1);
        if (i < CAP)
            g_adj[(size_t)c * CAP + i] = make_int2(row[e], __float_as_int(ew[e]));
    }
    grid_barrier();

    // ---- phase 2: degrees -> dinv, fused prescale h_hat0 = dinv*x -> g_h1
    {
        int gwarp = tid >> 5;
        int lane = threadIdx.x & 31;
        const float2* __restrict__ x2 = reinterpret_cast<const float2*>(x);
        float2* __restrict__ hp2 = reinterpret_cast<float2*>(g_h1);
        for (int n = gwarp; n < N_NODES; n += NWARPS) {
            int cnt = min(g_cnt_in[n], CAP);
            const int2* adj = g_adj + (size_t)n * CAP;
            float d = 0.0f;
            for (int k = lane; k < cnt; k += 32)
                d += __int_as_float(adj[k].y);
#pragma unroll
            for (int off = 16; off > 0; off >>= 1)
                d += __shfl_xor_sync(0xFFFFFFFFu, d, off);
            d += 1.0f;   // self loop
            float dv = (d > 0.0f) ? rsqrtf(d) : 0.0f;
            if (lane == 0) g_dinv[n] = dv;
            float2 v = x2[(size_t)n * 32 + lane];
            v.x *= dv; v.y *= dv;
            hp2[(size_t)n * 32 + lane] = v;
        }
    }
    grid_barrier();

    // ---- phases 3-5: K=3 propagation in scaled rep; hop 3 fuses pool ----
    hop_phase<false>(g_h1, g_h0, batch);   // h_hat0 -> h_hat1
    grid_barrier();
    hop_phase<false>(g_h0, g_h1, batch);   // h_hat1 -> h_hat2
    grid_barrier();
    hop_phase<true >(g_h1, g_h0 /*unused*/, batch);  // h_hat2 -> pooled h3
    grid_barrier();

    // ---- phase 6: head (grid-stride over graphs) + invariant restoration ----
    for (int g = blockIdx.x; g < G_GRAPHS; g += NBLK) {
        int j = threadIdx.x;

        __shared__ int   s_bounds[2];
        __shared__ float s_bufA[F_DIM];
        __shared__ float s_bufB[F_DIM];
        __shared__ float s_o[C_CLS];

        if (j < 2) {  // lower_bound(batch, g) / lower_bound(batch, g+1)
            int target = g + j;
            int lo = 0, hiN = N_NODES;
            while (lo < hiN) {
                int mid = (lo + hiN) >> 1;
                if (batch[mid] < target) lo = mid + 1; else hiN = mid;
            }
            s_bounds[j] = lo;
        }
        __syncthreads();

        if (j < F_DIM) {
            float cnt = (float)(s_bounds[1] - s_bounds[0]);
            s_bufA[j] = g_s[g * F_DIM + j] / fmaxf(cnt, 1.0f);   // mean
            g_s[g * F_DIM + j] = 0.0f;   // restore entry invariant for next call
        }
        __syncthreads();

        if (j < F_DIM) {
            float acc = conv_b[j];
#pragma unroll
            for (int f = 0; f < F_DIM; f++) acc += s_bufA[f] * conv_w[f * F_DIM + j];
            s_bufB[j] = acc;                                     // conv out
        }
        __syncthreads();

        if (j < F_DIM) {
            float acc = lin1_b[j];
#pragma unroll
            for (int f = 0; f < F_DIM; f++) acc += s_bufB[f] * lin1_w[f * F_DIM + j];
            s_bufA[j] = fmaxf(acc, 0.0f);                        // relu(lin1)
        }
        __syncthreads();

        if (j < C_CLS) {
            float acc = lin2_b[j];
#pragma unroll
            for (int f = 0; f < F_DIM; f++) acc += s_bufA[f] * lin2_w[f * C_CLS + j];
            s_o[j] = acc;
        }
        __syncthreads();

        if (j < C_CLS) {
            float m = -1e30f;
#pragma unroll
            for (int c = 0; c < C_CLS; c++) m = fmaxf(m, s_o[c]);
            float sum = 0.0f;
#pragma unroll
            for (int c = 0; c < C_CLS; c++) sum += __expf(s_o[c] - m);
            out[g * C_CLS + j] = s_o[j] - m - __logf(sum);
        }
        __syncthreads();   // protect smem reuse across loop iterations
    }

    // restore counter invariant for the next call (runs concurrently with
    // other blocks' head work; next kernel launch orders after this one)
    for (int i = tid; i < N_NODES; i += stride) g_cnt_in[i] = 0;
}

// ---------------------------------------------------------------------------
extern "C" void kernel_launch(void* const* d_in, const int* in_sizes, int n_in,
                              void* d_out, int out_size) {
    const float* x      = (const float*)d_in[0];   // [N, 64]
    const int*   eidx   = (const int*)d_in[1];     // [2, E]
    const float* ew     = (const float*)d_in[2];   // [E]
    const int*   batch  = (const int*)d_in[3];     // [N], sorted
    const float* conv_w = (const float*)d_in[4];
    const float* conv_b = (const float*)d_in[5];
    const float* lin1_w = (const float*)d_in[6];
    const float* lin1_b = (const float*)d_in[7];
    const float* lin2_w = (const float*)d_in[8];
    const float* lin2_b = (const float*)d_in[9];
    float* out = (float*)d_out;                    // [512, 10]

    sgc_persistent_kernel<<<NBLK, TPB>>>(x, eidx, ew, batch,
                                         conv_w, conv_b, lin1_w, lin1_b,
                                         lin2_w, lin2_b, out);
}

// round 15
// speedup vs baseline: 1.0150x; 1.0150x over previous
#include <cuda_runtime.h>
#include <math.h>

#define N_NODES   100000
#define N_EDGES   1600000
#define F_DIM     64
#define C_CLS     10
#define G_GRAPHS  512
#define CAP       64        // max in-degree (Poisson mean 16; P(>64) ~ 1e-20)
#define NBLK      592       // 148 SMs x 4 co-resident blocks (launch_bounds)
#define TPB       256
#define NWARPS    (NBLK * TPB / 32)
#define LEAVES    37        // tree barrier: 592 = 37 leaves x 16 blocks
#define LEAF_SZ   16

// Scratch (device globals: zero-initialized at module load; no runtime alloc)
__device__ float    g_h0[N_NODES * F_DIM];
__device__ float    g_h1[N_NODES * F_DIM];
__device__ float    g_dinv[N_NODES];
__device__ int      g_cnt_in[N_NODES];     // invariant: zero at kernel entry
__device__ int2     g_adj[(size_t)N_NODES * CAP];   // {src, raw weight bits}
__device__ float    g_s[G_GRAPHS * F_DIM]; // invariant: zero at kernel entry
__device__ unsigned g_leaf[LEAVES];        // monotonic; never reset
__device__ unsigned g_root;                // monotonic; never reset

static __device__ __forceinline__ void red_add_v4(float* dst, float4 v) {
    asm volatile("red.global.add.v4.f32 [%0], {%1, %2, %3, %4};"
                 :: "l"(dst), "f"(v.x), "f"(v.y), "f"(v.z), "f"(v.w)
                 : "memory");
}

// Two-level grid barrier, monotonic counters (no reset across graph replays).
// Arrivals: 16 serialized atomics per leaf (37 leaves in parallel) + 37 on
// the root, vs 592 serialized on one address for a flat barrier. The wait
// polls the root with a volatile LOAD (reads don't serialize at the LTS).
static __device__ __forceinline__ void grid_barrier() {
    __threadfence();                 // release (all threads)
    __syncthreads();
    if (threadIdx.x == 0) {
        int leaf = blockIdx.x >> 4;                       // 16 blocks / leaf
        unsigned t = atomicAdd(&g_leaf[leaf], 1u);
        unsigned round = t >> 4;
        if ((t & (LEAF_SZ - 1u)) == LEAF_SZ - 1u)         // last in leaf
            atomicAdd(&g_root, 1u);
        unsigned target = (round + 1u) * LEAVES;
        volatile unsigned* r = &g_root;
        while (*r < target) __nanosleep(32);
    }
    __syncthreads();
    __threadfence();                 // acquire (all threads)
}

// ---------------------------------------------------------------------------
// Hop in SCALED representation: input is h_hat = dinv .* h.
//   acc    = h_hat[c] + sum_e ew * h_hat[src]
//   !POOL: h_hat_out[c] = dinv[c]^2 * acc
//   POOL:  h_final[c]   = dinv[c]   * acc  -> red-add into g_s[batch[c]]
template <bool POOL>
static __device__ void hop_phase(const float* __restrict__ hin,
                                 float* __restrict__ hout,
                                 const int* __restrict__ batch) {
    int gwarp = (blockIdx.x * TPB + threadIdx.x) >> 5;
    int lane = threadIdx.x & 31;
    int half = lane >> 4;
    int sub = lane & 15;
    const float4* __restrict__ hin4 = reinterpret_cast<const float4*>(hin);
    float4* __restrict__ hout4 = reinterpret_cast<float4*>(hout);

    for (int base = gwarp * 2; base < N_NODES; base += NWARPS * 2) {
        int n = base + half;   // N_NODES even -> both halves always valid

        float dv = g_dinv[n];
        float4 acc = hin4[(size_t)n * 16 + sub];   // self contribution

        int cnt = min(g_cnt_in[n], CAP);
        const int2* adj = g_adj + (size_t)n * CAP;

        for (int k = 0; k < cnt; k += 4) {
            int4 p0 = *reinterpret_cast<const int4*>(adj + k);
            int4 p1 = *reinterpret_cast<const int4*>(adj + k + 2);
            int   s[4] = { p0.x, p0.z, p1.x, p1.z };
            float w[4] = { __int_as_float(p0.y), __int_as_float(p0.w),
                           __int_as_float(p1.y), __int_as_float(p1.w) };

            float4 u[4];
#pragma unroll
            for (int i = 0; i < 4; i++) {
                if (k + i >= cnt) w[i] = 0.0f;          // neutralize overshoot
                unsigned su = (unsigned)s[i];
                int src = (su < (unsigned)N_NODES) ? (int)su : 0;
                u[i] = hin4[(size_t)src * 16 + sub];    // 4 gathers in flight
            }
#pragma unroll
            for (int i = 0; i < 4; i++) {
                acc.x = fmaf(w[i], u[i].x, acc.x);
                acc.y = fmaf(w[i], u[i].y, acc.y);
                acc.z = fmaf(w[i], u[i].z, acc.z);
                acc.w = fmaf(w[i], u[i].w, acc.w);
            }
        }

        float sc = POOL ? dv : (dv * dv);
        acc.x *= sc; acc.y *= sc; acc.z *= sc; acc.w *= sc;

        if (POOL) {
            int b = batch[n];
            red_add_v4(&g_s[b * F_DIM + sub * 4], acc);
        } else {
            hout4[(size_t)n * 16 + sub] = acc;
        }
    }
}

// ---------------------------------------------------------------------------
// ONE persistent kernel. Entry invariant: g_cnt_in and g_s are all zero
// (zero-init at load; re-established at the tail of every call).
__global__ void __launch_bounds__(TPB, 4)
sgc_persistent_kernel(const float* __restrict__ x,
                      const int* __restrict__ eidx,
                      const float* __restrict__ ew,
                      const int* __restrict__ batch,
                      const float* __restrict__ conv_w,
                      const float* __restrict__ conv_b,
                      const float* __restrict__ lin1_w,
                      const float* __restrict__ lin1_b,
                      const float* __restrict__ lin2_w,
                      const float* __restrict__ lin2_b,
                      float* __restrict__ out) {
    const int tid = blockIdx.x * TPB + threadIdx.x;
    const int stride = NBLK * TPB;
    const int* row = eidx;             // edge_index[0]
    const int* col = eidx + N_EDGES;   // edge_index[1]

    // ---- phase 1: build in-adjacency buckets (counters pre-zeroed) ----
    for (int e = tid; e < N_EDGES; e += stride) {
        int c = col[e];
        int i = atomicAdd(&g_cnt_in[c], 1);
        if (i < CAP)
            g_adj[(size_t)c * CAP + i] = make_int2(row[e], __float_as_int(ew[e]));
    }
    grid_barrier();

    // ---- phase 2: degrees -> dinv, fused prescale h_hat0 = dinv*x -> g_h1
    {
        int gwarp = tid >> 5;
        int lane = threadIdx.x & 31;
        const float2* __restrict__ x2 = reinterpret_cast<const float2*>(x);
        float2* __restrict__ hp2 = reinterpret_cast<float2*>(g_h1);
        for (int n = gwarp; n < N_NODES; n += NWARPS) {
            int cnt = min(g_cnt_in[n], CAP);
            const int2* adj = g_adj + (size_t)n * CAP;
            float d = 0.0f;
            for (int k = lane; k < cnt; k += 32)
                d += __int_as_float(adj[k].y);
#pragma unroll
            for (int off = 16; off > 0; off >>= 1)
                d += __shfl_xor_sync(0xFFFFFFFFu, d, off);
            d += 1.0f;   // self loop
            float dv = (d > 0.0f) ? rsqrtf(d) : 0.0f;
            if (lane == 0) g_dinv[n] = dv;
            float2 v = x2[(size_t)n * 32 + lane];
            v.x *= dv; v.y *= dv;
            hp2[(size_t)n * 32 + lane] = v;
        }
    }
    grid_barrier();

    // ---- phases 3-5: K=3 propagation in scaled rep; hop 3 fuses pool ----
    hop_phase<false>(g_h1, g_h0, batch);   // h_hat0 -> h_hat1
    grid_barrier();
    hop_phase<false>(g_h0, g_h1, batch);   // h_hat1 -> h_hat2
    grid_barrier();
    hop_phase<true >(g_h1, g_h0 /*unused*/, batch);  // h_hat2 -> pooled h3
    grid_barrier();

    // ---- phase 6: head (grid-stride over graphs) + invariant restoration ----
    for (int g = blockIdx.x; g < G_GRAPHS; g += NBLK) {
        int j = threadIdx.x;

        __shared__ int   s_bounds[2];
        __shared__ float s_bufA[F_DIM];
        __shared__ float s_bufB[F_DIM];
        __shared__ float s_o[C_CLS];

        if (j < 2) {  // lower_bound(batch, g) / lower_bound(batch, g+1)
            int target = g + j;
            int lo = 0, hiN = N_NODES;
            while (lo < hiN) {
                int mid = (lo + hiN) >> 1;
                if (batch[mid] < target) lo = mid + 1; else hiN = mid;
            }
            s_bounds[j] = lo;
        }
        __syncthreads();

        if (j < F_DIM) {
            float cnt = (float)(s_bounds[1] - s_bounds[0]);
            s_bufA[j] = g_s[g * F_DIM + j] / fmaxf(cnt, 1.0f);   // mean
            g_s[g * F_DIM + j] = 0.0f;   // restore entry invariant for next call
        }
        __syncthreads();

        if (j < F_DIM) {
            float acc = conv_b[j];
#pragma unroll
            for (int f = 0; f < F_DIM; f++) acc += s_bufA[f] * conv_w[f * F_DIM + j];
            s_bufB[j] = acc;                                     // conv out
        }
        __syncthreads();

        if (j < F_DIM) {
            float acc = lin1_b[j];
#pragma unroll
            for (int f = 0; f < F_DIM; f++) acc += s_bufB[f] * lin1_w[f * F_DIM + j];
            s_bufA[j] = fmaxf(acc, 0.0f);                        // relu(lin1)
        }
        __syncthreads();

        if (j < C_CLS) {
            float acc = lin2_b[j];
#pragma unroll
            for (int f = 0; f < F_DIM; f++) acc += s_bufA[f] * lin2_w[f * C_CLS + j];
            s_o[j] = acc;
        }
        __syncthreads();

        if (j < C_CLS) {
            float m = -1e30f;
#pragma unroll
            for (int c = 0; c < C_CLS; c++) m = fmaxf(m, s_o[c]);
            float sum = 0.0f;
#pragma unroll
            for (int c = 0; c < C_CLS; c++) sum += __expf(s_o[c] - m);
            out[g * C_CLS + j] = s_o[j] - m - __logf(sum);
        }
        __syncthreads();   // protect smem reuse across loop iterations
    }

    // restore counter invariant for the next call (runs concurrently with
    // other blocks' head work; next kernel launch orders after this one)
    for (int i = tid; i < N_NODES; i += stride) g_cnt_in[i] = 0;
}

// ---------------------------------------------------------------------------
extern "C" void kernel_launch(void* const* d_in, const int* in_sizes, int n_in,
                              void* d_out, int out_size) {
    const float* x      = (const float*)d_in[0];   // [N, 64]
    const int*   eidx   = (const int*)d_in[1];     // [2, E]
    const float* ew     = (const float*)d_in[2];   // [E]
    const int*   batch  = (const int*)d_in[3];     // [N], sorted
    const float* conv_w = (const float*)d_in[4];
    const float* conv_b = (const float*)d_in[5];
    const float* lin1_w = (const float*)d_in[6];
    const float* lin1_b = (const float*)d_in[7];
    const float* lin2_w = (const float*)d_in[8];
    const float* lin2_b = (const float*)d_in[9];
    float* out = (float*)d_out;                    // [512, 10]

    sgc_persistent_kernel<<<NBLK, TPB>>>(x, eidx, ew, batch,
                                         conv_w, conv_b, lin1_w, lin1_b,
                                         lin2_w, lin2_b, out);
}